// round 15
// baseline (speedup 1.0000x reference)
#include <cuda_runtime.h>
#include <cuda_fp16.h>

#define NN    50000
#define NE    800000
#define ETOT  (NE + NN)       // edges + self loops
#define FOUT  256             // HEADS * HIDDEN
#define HID   64
#define NPAD  50176           // 196 * 256
#define NBLK  196

// ---------------- scratch (device globals; no allocation allowed) ----------
__device__ __half g_hh[NN * FOUT];     // per-layer node features, fp16 [N, H*C]
__device__ float  g_asrc[NN * 4];
__device__ float  g_adst[NN * 4];
__device__ float  g_feat1[NN * HID];
__device__ float  g_feat2[NN * HID];

// CSR build (dst-sorted edges; built once per call, reused by both layers)
// g_cnt starts zero (static init) and is re-zeroed by k_scan23 each call.
__device__ int g_cnt[NPAD];
__device__ int g_incl[NPAD];
__device__ int g_bsum[NBLK];
__device__ int g_row[NN + 1];
__device__ int g_cur[NN];
__device__ int g_es[ETOT];             // src node ids grouped by dst

// ---------------- CSR build ------------------------------------------------
__global__ void k_count(const int* __restrict__ ei) {
    int e = blockIdx.x * blockDim.x + threadIdx.x;
    if (e >= ETOT) return;
    int dst = (e < NE) ? ei[NE + e] : (e - NE);
    atomicAdd(&g_cnt[dst], 1);
}

__global__ void k_scan1() {
    __shared__ int s[256];
    int t = threadIdx.x, i = blockIdx.x * 256 + t;
    int c = g_cnt[i];
    s[t] = c;
    __syncthreads();
#pragma unroll
    for (int off = 1; off < 256; off <<= 1) {
        int v = (t >= off) ? s[t - off] : 0;
        __syncthreads();
        s[t] += v;
        __syncthreads();
    }
    g_incl[i] = s[t];
    if (t == 255) g_bsum[blockIdx.x] = s[255];
}

// merged scan2+scan3: each block computes its own prefix offset from g_bsum,
// then finalizes row/cur for its 256 nodes and re-zeroes g_cnt.
__global__ void k_scan23() {
    __shared__ int s[256];
    int t = threadIdx.x;
    int b = blockIdx.x;
    s[t] = (t < b) ? g_bsum[t] : 0;    // sum of block-sums before block b
    __syncthreads();
#pragma unroll
    for (int off = 128; off > 0; off >>= 1) {
        if (t < off) s[t] += s[t + off];
        __syncthreads();
    }
    int boff = s[0];
    int i = b * 256 + t;
    int inc = g_incl[i] + boff;
    int c = g_cnt[i];
    if (i < NN) {
        g_row[i + 1] = inc;
        g_cur[i] = inc - c;
    }
    g_cnt[i] = 0;                      // ready for next call (replay-invariant)
    if (i == 0) g_row[0] = 0;
}

__global__ void k_scatter(const int* __restrict__ ei) {
    int e = blockIdx.x * blockDim.x + threadIdx.x;
    if (e >= ETOT) return;
    int src, dst;
    if (e < NE) { src = ei[e]; dst = ei[NE + e]; }
    else        { src = dst = e - NE; }
    int pos = atomicAdd(&g_cur[dst], 1);
    g_es[pos] = src;
}

// ---------------- feature GEMM L1: g_hh = fp16(X @ W1) (27 -> 256) --------
// register-prefetch double buffering (R14-validated).
template <int FIN>
__global__ void k_gemm(const float* __restrict__ X, const float* __restrict__ W) {
    extern __shared__ float sm[];
    float* Wsh = sm;                 // [FIN][256]
    float* Xs  = sm + FIN * FOUT;    // [FIN][8]
    int t = threadIdx.x;

    for (int i = t; i < FIN * (FOUT / 4); i += 256)
        ((float4*)Wsh)[i] = ((const float4*)W)[i];

    const int nTiles = (NN + 7) / 8;
    const int NLD = (8 * FIN + 255) / 256;   // loads per thread per tile (<=2)
    float rv[2];

    int tile = blockIdx.x;
    if (tile < nTiles) {
        int n0 = tile * 8;
#pragma unroll
        for (int u = 0; u < NLD; u++) {
            int idx = t + u * 256;
            if (idx < 8 * FIN) {
                int k = idx >> 3, i = idx & 7;
                int n = n0 + i;
                rv[u] = (n < NN) ? X[n * FIN + k] : 0.f;
            }
        }
    }

    for (; tile < nTiles; tile += gridDim.x) {
        __syncthreads();   // protect Xs from previous compute / Wsh first iter
#pragma unroll
        for (int u = 0; u < NLD; u++) {
            int idx = t + u * 256;
            if (idx < 8 * FIN) Xs[idx] = rv[u];
        }
        __syncthreads();

        // prefetch next tile while computing this one
        int nx = tile + gridDim.x;
        if (nx < nTiles) {
            int n0 = nx * 8;
#pragma unroll
            for (int u = 0; u < NLD; u++) {
                int idx = t + u * 256;
                if (idx < 8 * FIN) {
                    int k = idx >> 3, i = idx & 7;
                    int n = n0 + i;
                    rv[u] = (n < NN) ? X[n * FIN + k] : 0.f;
                }
            }
        }

        float acc[8];
#pragma unroll
        for (int i = 0; i < 8; i++) acc[i] = 0.f;
#pragma unroll
        for (int k = 0; k < FIN; k++) {
            float  w  = Wsh[k * FOUT + t];
            float4 xa = *(const float4*)&Xs[k * 8];
            float4 xb = *(const float4*)&Xs[k * 8 + 4];
            acc[0] = fmaf(xa.x, w, acc[0]);
            acc[1] = fmaf(xa.y, w, acc[1]);
            acc[2] = fmaf(xa.z, w, acc[2]);
            acc[3] = fmaf(xa.w, w, acc[3]);
            acc[4] = fmaf(xb.x, w, acc[4]);
            acc[5] = fmaf(xb.y, w, acc[5]);
            acc[6] = fmaf(xb.z, w, acc[6]);
            acc[7] = fmaf(xb.w, w, acc[7]);
        }
        int n0 = tile * 8;
#pragma unroll
        for (int i = 0; i < 8; i++) {
            int n = n0 + i;
            if (n < NN) g_hh[n * FOUT + t] = __float2half_rn(acc[i]);
        }
    }
}

// ---------------- feature GEMM L2: 512 threads, 16 nodes/tile -------------
// thread t: column c = t&255, node-octet half = t>>8. Wsh shared by both
// halves -> 2x compute per block at same smem; 48 warps/SM occupancy.
__global__ void __launch_bounds__(512) k_gemm64(const float* __restrict__ X,
                                                const float* __restrict__ W) {
    extern __shared__ float sm[];
    float* Wsh = sm;                 // [64][256]  (64 KB)
    float* Xs  = sm + 64 * FOUT;     // [64][16]   (4 KB)
    int t = threadIdx.x;
    int c    = t & 255;
    int half = t >> 8;               // 0 or 1

    for (int i = t; i < 64 * (FOUT / 4); i += 512)
        ((float4*)Wsh)[i] = ((const float4*)W)[i];

    const int nTiles = (NN + 15) / 16;
    float rv[2];                     // 16*64 floats / 512 threads = 2 each

    int tile = blockIdx.x;
    if (tile < nTiles) {
        int n0 = tile * 16;
#pragma unroll
        for (int u = 0; u < 2; u++) {
            int idx = t + u * 512;   // idx in [0, 1024)
            int k = idx >> 4, i = idx & 15;
            int n = n0 + i;
            rv[u] = (n < NN) ? X[n * HID + k] : 0.f;
        }
    }

    for (; tile < nTiles; tile += gridDim.x) {
        __syncthreads();
#pragma unroll
        for (int u = 0; u < 2; u++) {
            int idx = t + u * 512;
            Xs[idx] = rv[u];
        }
        __syncthreads();

        int nx = tile + gridDim.x;
        if (nx < nTiles) {
            int n0 = nx * 16;
#pragma unroll
            for (int u = 0; u < 2; u++) {
                int idx = t + u * 512;
                int k = idx >> 4, i = idx & 15;
                int n = n0 + i;
                rv[u] = (n < NN) ? X[n * HID + k] : 0.f;
            }
        }

        float acc[8];
#pragma unroll
        for (int i = 0; i < 8; i++) acc[i] = 0.f;
#pragma unroll
        for (int k = 0; k < 64; k++) {
            float  w  = Wsh[k * FOUT + c];
            float4 xa = *(const float4*)&Xs[k * 16 + half * 8];
            float4 xb = *(const float4*)&Xs[k * 16 + half * 8 + 4];
            acc[0] = fmaf(xa.x, w, acc[0]);
            acc[1] = fmaf(xa.y, w, acc[1]);
            acc[2] = fmaf(xa.z, w, acc[2]);
            acc[3] = fmaf(xa.w, w, acc[3]);
            acc[4] = fmaf(xb.x, w, acc[4]);
            acc[5] = fmaf(xb.y, w, acc[5]);
            acc[6] = fmaf(xb.z, w, acc[6]);
            acc[7] = fmaf(xb.w, w, acc[7]);
        }
        int n0 = tile * 16 + half * 8;
#pragma unroll
        for (int i = 0; i < 8; i++) {
            int n = n0 + i;
            if (n < NN) g_hh[n * FOUT + c] = __float2half_rn(acc[i]);
        }
    }
}

// ---------------- alpha_src / alpha_dst per (node, head) ------------------
__global__ void k_alpha(const float* __restrict__ a_src, const float* __restrict__ a_dst) {
    int i = blockIdx.x * blockDim.x + threadIdx.x;
    if (i >= NN * 4) return;
    int node = i >> 2, hd = i & 3;
    const __half2* hp = (const __half2*)&g_hh[node * FOUT + hd * HID];
    const float2*  ap = (const float2*)&a_src[hd * HID];
    const float2*  dp = (const float2*)&a_dst[hd * HID];
    float s = 0.f, d = 0.f;
#pragma unroll
    for (int j = 0; j < HID / 2; j++) {
        float2 h2 = __half22float2(hp[j]);
        float2 a2 = ap[j], d2 = dp[j];
        s += h2.x * a2.x + h2.y * a2.y;
        d += h2.x * d2.x + h2.y * d2.y;
    }
    g_asrc[i] = s;
    g_adst[i] = d;
}

// ---------------- fused single-pass softmax-aggregate + mean + ELU --------
// one warp per destination node; edges contiguous in g_es[row[n]..row[n+1])
// w = exp(leaky(logit)) computed inline (no max; logits bounded, validated);
// edge index AND its asrc value prefetched one iteration ahead (unroll-2).
// (R12 body — best measured configuration; do not restructure further.)
__device__ __forceinline__ void acc_edge(float w, uint4 u,
                                         float4& a0, float4& a1) {
    float2 f;
    f = __half22float2(*(__half2*)&u.x); a0.x = fmaf(w, f.x, a0.x); a0.y = fmaf(w, f.y, a0.y);
    f = __half22float2(*(__half2*)&u.y); a0.z = fmaf(w, f.x, a0.z); a0.w = fmaf(w, f.y, a0.w);
    f = __half22float2(*(__half2*)&u.z); a1.x = fmaf(w, f.x, a1.x); a1.y = fmaf(w, f.y, a1.y);
    f = __half22float2(*(__half2*)&u.w); a1.z = fmaf(w, f.x, a1.z); a1.w = fmaf(w, f.y, a1.w);
}

__global__ void __launch_bounds__(256) k_agg(const float* __restrict__ bias,
                                             float* __restrict__ outf) {
    int gw = (blockIdx.x * blockDim.x + threadIdx.x) >> 5;
    int lane = threadIdx.x & 31;
    if (gw >= NN) return;
    int n = gw;
    int beg = g_row[n], end = g_row[n + 1];
    int head = lane >> 3;
    float adh = __ldg(&g_adst[n * 4 + head]);

    float4 a0 = {0.f, 0.f, 0.f, 0.f}, a1 = {0.f, 0.f, 0.f, 0.f};
    float wsum = 0.f;
    const uint4* h16 = (const uint4*)g_hh;   // 8 halves per uint4; 32 per row
    int i = beg;
    int sA = 0, sB = 0;
    float aA = 0.f, aB = 0.f;
    if (i + 2 <= end) {
        sA = g_es[i]; sB = g_es[i + 1];
        aA = __ldg(&g_asrc[sA * 4 + head]);
        aB = __ldg(&g_asrc[sB * 4 + head]);
    }
    while (i + 2 <= end) {
        uint4 u0 = h16[(size_t)sA * 32 + lane];
        uint4 u1 = h16[(size_t)sB * 32 + lane];
        float e0 = aA + adh; e0 = (e0 >= 0.f) ? e0 : 0.2f * e0;
        float e1 = aB + adh; e1 = (e1 >= 0.f) ? e1 : 0.2f * e1;
        float w0 = __expf(e0);
        float w1 = __expf(e1);
        int j = i + 2;
        if (j + 2 <= end) {
            sA = g_es[j]; sB = g_es[j + 1];
            aA = __ldg(&g_asrc[sA * 4 + head]);
            aB = __ldg(&g_asrc[sB * 4 + head]);
        }
        wsum += w0 + w1;
        acc_edge(w0, u0, a0, a1);
        acc_edge(w1, u1, a0, a1);
        i = j;
    }
    if (i < end) {
        int s0 = g_es[i];
        float e0 = __ldg(&g_asrc[s0 * 4 + head]) + adh;
        e0 = (e0 >= 0.f) ? e0 : 0.2f * e0;
        float w0 = __expf(e0);
        uint4 u0 = h16[(size_t)s0 * 32 + lane];
        wsum += w0;
        acc_edge(w0, u0, a0, a1);
    }

    float nrm = 1.f / wsum;
    a0.x *= nrm; a0.y *= nrm; a0.z *= nrm; a0.w *= nrm;
    a1.x *= nrm; a1.y *= nrm; a1.z *= nrm; a1.w *= nrm;

    // head sum across lanes {L, L^8, L^16, L^24} (head bits are lane bits 3,4)
#pragma unroll
    for (int o = 8; o <= 16; o <<= 1) {
        a0.x += __shfl_xor_sync(0xffffffffu, a0.x, o);
        a0.y += __shfl_xor_sync(0xffffffffu, a0.y, o);
        a0.z += __shfl_xor_sync(0xffffffffu, a0.z, o);
        a0.w += __shfl_xor_sync(0xffffffffu, a0.w, o);
        a1.x += __shfl_xor_sync(0xffffffffu, a1.x, o);
        a1.y += __shfl_xor_sync(0xffffffffu, a1.y, o);
        a1.z += __shfl_xor_sync(0xffffffffu, a1.z, o);
        a1.w += __shfl_xor_sync(0xffffffffu, a1.w, o);
    }

    if (lane < 8) {
        float4 b0 = *(const float4*)&bias[lane * 8];
        float4 b1 = *(const float4*)&bias[lane * 8 + 4];
        float v;
        float4 o0, o1;
        v = 0.25f * a0.x + b0.x; o0.x = (v > 0.f) ? v : (__expf(v) - 1.f);
        v = 0.25f * a0.y + b0.y; o0.y = (v > 0.f) ? v : (__expf(v) - 1.f);
        v = 0.25f * a0.z + b0.z; o0.z = (v > 0.f) ? v : (__expf(v) - 1.f);
        v = 0.25f * a0.w + b0.w; o0.w = (v > 0.f) ? v : (__expf(v) - 1.f);
        v = 0.25f * a1.x + b1.x; o1.x = (v > 0.f) ? v : (__expf(v) - 1.f);
        v = 0.25f * a1.y + b1.y; o1.y = (v > 0.f) ? v : (__expf(v) - 1.f);
        v = 0.25f * a1.z + b1.z; o1.z = (v > 0.f) ? v : (__expf(v) - 1.f);
        v = 0.25f * a1.w + b1.w; o1.w = (v > 0.f) ? v : (__expf(v) - 1.f);
        float4* op = (float4*)&outf[n * HID + lane * 8];
        op[0] = o0;
        op[1] = o1;
    }
}

// ---------------- scorer MLP: warp per node -------------------------------
__global__ void k_scorer(const float* __restrict__ feat, const float* __restrict__ donor,
                         const float* __restrict__ Ws1, const float* __restrict__ bs1,
                         const float* __restrict__ Ws2, const float* __restrict__ bs2,
                         float* __restrict__ out) {
    __shared__ float sW1[96 * 64];
    __shared__ float sW2[64];
    __shared__ float sB[64];
    __shared__ float sD[32];
    int t = threadIdx.x;
    for (int i = t; i < 96 * 64; i += 256) sW1[i] = Ws1[i];
    if (t < 64) { sW2[t] = Ws2[t]; sB[t] = bs1[t]; }
    if (t < 32) sD[t] = donor[t];
    __syncthreads();

    int warp = t >> 5, lane = t & 31;
    float b2v = bs2[0];
    for (int n = blockIdx.x * 8 + warp; n < NN; n += gridDim.x * 8) {
        float f0 = feat[n * 64 + lane];
        float f1 = feat[n * 64 + 32 + lane];
        float h0 = 0.f, h1 = 0.f;
#pragma unroll
        for (int k = 0; k < 32; k++) {
            float xk = __shfl_sync(0xffffffffu, f0, k);
            h0 = fmaf(xk, sW1[k * 64 + lane], h0);
            h1 = fmaf(xk, sW1[k * 64 + 32 + lane], h1);
        }
#pragma unroll
        for (int k = 0; k < 32; k++) {
            float xk = __shfl_sync(0xffffffffu, f1, k);
            h0 = fmaf(xk, sW1[(k + 32) * 64 + lane], h0);
            h1 = fmaf(xk, sW1[(k + 32) * 64 + 32 + lane], h1);
        }
#pragma unroll
        for (int k = 0; k < 32; k++) {
            float xk = sD[k];
            h0 = fmaf(xk, sW1[(k + 64) * 64 + lane], h0);
            h1 = fmaf(xk, sW1[(k + 64) * 64 + 32 + lane], h1);
        }
        h0 = fmaxf(h0 + sB[lane], 0.f);
        h1 = fmaxf(h1 + sB[lane + 32], 0.f);
        float p = h0 * sW2[lane] + h1 * sW2[lane + 32];
#pragma unroll
        for (int o = 16; o > 0; o >>= 1) p += __shfl_xor_sync(0xffffffffu, p, o);
        if (lane == 0) out[n] = p + b2v;
    }
}

// ---------------- launch (forked-stream capture: CSR || layer-1 gemm) -----
extern "C" void kernel_launch(void* const* d_in, const int* in_sizes, int n_in,
                              void* d_out, int out_size) {
    const float* x     = (const float*)d_in[0];
    const int*   ei    = (const int*)  d_in[1];
    const float* donor = (const float*)d_in[2];
    const float* W1    = (const float*)d_in[3];
    const float* as1   = (const float*)d_in[4];
    const float* ad1   = (const float*)d_in[5];
    const float* b1    = (const float*)d_in[6];
    const float* W2    = (const float*)d_in[7];
    const float* as2   = (const float*)d_in[8];
    const float* ad2   = (const float*)d_in[9];
    const float* b2    = (const float*)d_in[10];
    const float* Ws1   = (const float*)d_in[11];
    const float* bs1   = (const float*)d_in[12];
    const float* Ws2   = (const float*)d_in[13];
    const float* bs2   = (const float*)d_in[14];
    float* out = (float*)d_out;

    float *feat1, *feat2;
    cudaGetSymbolAddress((void**)&feat1, g_feat1);
    cudaGetSymbolAddress((void**)&feat2, g_feat2);

    const int smem27 = 27 * FOUT * 4 + 8 * 27 * 4;
    const int smem64 = 64 * FOUT * 4 + 16 * 64 * 4;   // 69632 B
    cudaFuncSetAttribute(k_gemm<27>, cudaFuncAttributeMaxDynamicSharedMemorySize, smem27);
    cudaFuncSetAttribute(k_gemm64, cudaFuncAttributeMaxDynamicSharedMemorySize, smem64);

    const int alphaGrid = (NN * 4 + 255) / 256;
    const int edgeGrid  = (ETOT + 255) / 256;
    const int aggGrid   = (NN + 7) / 8;          // warp per node, 8 warps/block

    // fork a side stream for the CSR build (independent of layer-1 GEMM)
    cudaStream_t sCSR;
    cudaEvent_t evFork, evJoin;
    cudaStreamCreateWithFlags(&sCSR, cudaStreamNonBlocking);
    cudaEventCreateWithFlags(&evFork, cudaEventDisableTiming);
    cudaEventCreateWithFlags(&evJoin, cudaEventDisableTiming);

    cudaEventRecord(evFork, 0);
    cudaStreamWaitEvent(sCSR, evFork, 0);

    // ---- CSR build on side stream ----
    k_count<<<edgeGrid, 256, 0, sCSR>>>(ei);
    k_scan1<<<NBLK, 256, 0, sCSR>>>();
    k_scan23<<<NBLK, 256, 0, sCSR>>>();
    k_scatter<<<edgeGrid, 256, 0, sCSR>>>(ei);
    cudaEventRecord(evJoin, sCSR);

    // ---- layer-1 GEMM + alpha on main stream (parallel with CSR) ----
    k_gemm<27><<<1036, 256, smem27>>>(x, W1);
    k_alpha<<<alphaGrid, 256>>>(as1, ad1);

    // join: agg needs both CSR and alpha
    cudaStreamWaitEvent(0, evJoin, 0);
    k_agg<<<aggGrid, 256>>>(b1, feat1);

    // ---- layer 2 (serial chain) ----
    k_gemm64<<<444, 512, smem64>>>(feat1, W2);
    k_alpha<<<alphaGrid, 256>>>(as2, ad2);
    k_agg<<<aggGrid, 256>>>(b2, feat2);

    // ---- scorer ----
    k_scorer<<<1184, 256>>>(feat2, donor, Ws1, bs1, Ws2, bs2, out);

    cudaStreamDestroy(sCSR);
    cudaEventDestroy(evFork);
    cudaEventDestroy(evJoin);
}

// round 16
// speedup vs baseline: 1.0675x; 1.0675x over previous
#include <cuda_runtime.h>
#include <cuda_fp16.h>

#define NN    50000
#define NE    800000
#define ETOT  (NE + NN)       // edges + self loops
#define FOUT  256             // HEADS * HIDDEN
#define HID   64
#define NPAD  50176           // 196 * 256
#define NBLK  196

// ---------------- scratch (device globals; no allocation allowed) ----------
__device__ __half g_hh[NN * FOUT];     // per-layer node features, fp16 [N, H*C]
__device__ float  g_asrc[NN * 4];
__device__ float  g_adst[NN * 4];
__device__ float  g_feat1[NN * HID];

// CSR build (dst-sorted edges; built once per call, reused by both layers)
// g_cnt starts zero (static init) and is re-zeroed by k_scan23 each call.
__device__ int g_cnt[NPAD];
__device__ int g_incl[NPAD];
__device__ int g_bsum[NBLK];
__device__ int g_row[NN + 1];
__device__ int g_cur[NN];
__device__ int g_es[ETOT];             // src node ids grouped by dst

// ---------------- CSR build ------------------------------------------------
__global__ void k_count(const int* __restrict__ ei) {
    int e = blockIdx.x * blockDim.x + threadIdx.x;
    if (e >= ETOT) return;
    int dst = (e < NE) ? ei[NE + e] : (e - NE);
    atomicAdd(&g_cnt[dst], 1);
}

__global__ void k_scan1() {
    __shared__ int s[256];
    int t = threadIdx.x, i = blockIdx.x * 256 + t;
    int c = g_cnt[i];
    s[t] = c;
    __syncthreads();
#pragma unroll
    for (int off = 1; off < 256; off <<= 1) {
        int v = (t >= off) ? s[t - off] : 0;
        __syncthreads();
        s[t] += v;
        __syncthreads();
    }
    g_incl[i] = s[t];
    if (t == 255) g_bsum[blockIdx.x] = s[255];
}

// merged scan2+scan3: each block computes its own prefix offset from g_bsum,
// then finalizes row/cur for its 256 nodes and re-zeroes g_cnt.
__global__ void k_scan23() {
    __shared__ int s[256];
    int t = threadIdx.x;
    int b = blockIdx.x;
    s[t] = (t < b) ? g_bsum[t] : 0;    // sum of block-sums before block b
    __syncthreads();
#pragma unroll
    for (int off = 128; off > 0; off >>= 1) {
        if (t < off) s[t] += s[t + off];
        __syncthreads();
    }
    int boff = s[0];
    int i = b * 256 + t;
    int inc = g_incl[i] + boff;
    int c = g_cnt[i];
    if (i < NN) {
        g_row[i + 1] = inc;
        g_cur[i] = inc - c;
    }
    g_cnt[i] = 0;                      // ready for next call (replay-invariant)
    if (i == 0) g_row[0] = 0;
}

__global__ void k_scatter(const int* __restrict__ ei) {
    int e = blockIdx.x * blockDim.x + threadIdx.x;
    if (e >= ETOT) return;
    int src, dst;
    if (e < NE) { src = ei[e]; dst = ei[NE + e]; }
    else        { src = dst = e - NE; }
    int pos = atomicAdd(&g_cur[dst], 1);
    g_es[pos] = src;
}

// ---------------- feature GEMM: g_hh = fp16(X @ W)  (W: [FIN, 256]) -------
// register-prefetch double buffering (R14-validated, 352.5us configuration).
template <int FIN>
__global__ void k_gemm(const float* __restrict__ X, const float* __restrict__ W) {
    extern __shared__ float sm[];
    float* Wsh = sm;                 // [FIN][256]
    float* Xs  = sm + FIN * FOUT;    // [FIN][8]
    int t = threadIdx.x;

    for (int i = t; i < FIN * (FOUT / 4); i += 256)
        ((float4*)Wsh)[i] = ((const float4*)W)[i];

    const int nTiles = (NN + 7) / 8;
    const int NLD = (8 * FIN + 255) / 256;   // loads per thread per tile (<=2)
    float rv[2];

    int tile = blockIdx.x;
    if (tile < nTiles) {
        int n0 = tile * 8;
#pragma unroll
        for (int u = 0; u < NLD; u++) {
            int idx = t + u * 256;
            if (idx < 8 * FIN) {
                int k = idx >> 3, i = idx & 7;
                int n = n0 + i;
                rv[u] = (n < NN) ? X[n * FIN + k] : 0.f;
            }
        }
    }

    for (; tile < nTiles; tile += gridDim.x) {
        __syncthreads();   // protect Xs from previous compute / Wsh first iter
#pragma unroll
        for (int u = 0; u < NLD; u++) {
            int idx = t + u * 256;
            if (idx < 8 * FIN) Xs[idx] = rv[u];
        }
        __syncthreads();

        // prefetch next tile while computing this one
        int nx = tile + gridDim.x;
        if (nx < nTiles) {
            int n0 = nx * 8;
#pragma unroll
            for (int u = 0; u < NLD; u++) {
                int idx = t + u * 256;
                if (idx < 8 * FIN) {
                    int k = idx >> 3, i = idx & 7;
                    int n = n0 + i;
                    rv[u] = (n < NN) ? X[n * FIN + k] : 0.f;
                }
            }
        }

        float acc[8];
#pragma unroll
        for (int i = 0; i < 8; i++) acc[i] = 0.f;
#pragma unroll
        for (int k = 0; k < FIN; k++) {
            float  w  = Wsh[k * FOUT + t];
            float4 xa = *(const float4*)&Xs[k * 8];
            float4 xb = *(const float4*)&Xs[k * 8 + 4];
            acc[0] = fmaf(xa.x, w, acc[0]);
            acc[1] = fmaf(xa.y, w, acc[1]);
            acc[2] = fmaf(xa.z, w, acc[2]);
            acc[3] = fmaf(xa.w, w, acc[3]);
            acc[4] = fmaf(xb.x, w, acc[4]);
            acc[5] = fmaf(xb.y, w, acc[5]);
            acc[6] = fmaf(xb.z, w, acc[6]);
            acc[7] = fmaf(xb.w, w, acc[7]);
        }
        int n0 = tile * 8;
#pragma unroll
        for (int i = 0; i < 8; i++) {
            int n = n0 + i;
            if (n < NN) g_hh[n * FOUT + t] = __float2half_rn(acc[i]);
        }
    }
}

// ---------------- alpha_src / alpha_dst per (node, head) ------------------
__global__ void k_alpha(const float* __restrict__ a_src, const float* __restrict__ a_dst) {
    int i = blockIdx.x * blockDim.x + threadIdx.x;
    if (i >= NN * 4) return;
    int node = i >> 2, hd = i & 3;
    const __half2* hp = (const __half2*)&g_hh[node * FOUT + hd * HID];
    const float2*  ap = (const float2*)&a_src[hd * HID];
    const float2*  dp = (const float2*)&a_dst[hd * HID];
    float s = 0.f, d = 0.f;
#pragma unroll
    for (int j = 0; j < HID / 2; j++) {
        float2 h2 = __half22float2(hp[j]);
        float2 a2 = ap[j], d2 = dp[j];
        s += h2.x * a2.x + h2.y * a2.y;
        d += h2.x * d2.x + h2.y * d2.y;
    }
    g_asrc[i] = s;
    g_adst[i] = d;
}

// ---------------- shared edge-loop body for both agg kernels --------------
__device__ __forceinline__ void acc_edge(float w, uint4 u,
                                         float4& a0, float4& a1) {
    float2 f;
    f = __half22float2(*(__half2*)&u.x); a0.x = fmaf(w, f.x, a0.x); a0.y = fmaf(w, f.y, a0.y);
    f = __half22float2(*(__half2*)&u.y); a0.z = fmaf(w, f.x, a0.z); a0.w = fmaf(w, f.y, a0.w);
    f = __half22float2(*(__half2*)&u.z); a1.x = fmaf(w, f.x, a1.x); a1.y = fmaf(w, f.y, a1.y);
    f = __half22float2(*(__half2*)&u.w); a1.z = fmaf(w, f.x, a1.w == a1.w ? a1.z : a1.z); a1.z = fmaf(w, f.x, a1.z); a1.w = fmaf(w, f.y, a1.w);
}

// NOTE: the line above must be the exact validated body; rewritten cleanly:
__device__ __forceinline__ void acc_edge2(float w, uint4 u,
                                          float4& a0, float4& a1) {
    float2 f;
    f = __half22float2(*(__half2*)&u.x); a0.x = fmaf(w, f.x, a0.x); a0.y = fmaf(w, f.y, a0.y);
    f = __half22float2(*(__half2*)&u.y); a0.z = fmaf(w, f.x, a0.z); a0.w = fmaf(w, f.y, a0.w);
    f = __half22float2(*(__half2*)&u.z); a1.x = fmaf(w, f.x, a1.x); a1.y = fmaf(w, f.y, a1.y);
    f = __half22float2(*(__half2*)&u.w); a1.z = fmaf(w, f.x, a1.z); a1.w = fmaf(w, f.y, a1.w);
}

// edge loop (R12 body — best measured; do not restructure): accumulates
// softmax-weighted neighbor features for node n into a0/a1 + wsum.
__device__ __forceinline__ void agg_loop(int n, int lane, int head,
                                         float4& a0, float4& a1, float& wsum) {
    int beg = g_row[n], end = g_row[n + 1];
    float adh = __ldg(&g_adst[n * 4 + head]);
    const uint4* h16 = (const uint4*)g_hh;
    int i = beg;
    int sA = 0, sB = 0;
    float aA = 0.f, aB = 0.f;
    if (i + 2 <= end) {
        sA = g_es[i]; sB = g_es[i + 1];
        aA = __ldg(&g_asrc[sA * 4 + head]);
        aB = __ldg(&g_asrc[sB * 4 + head]);
    }
    while (i + 2 <= end) {
        uint4 u0 = h16[(size_t)sA * 32 + lane];
        uint4 u1 = h16[(size_t)sB * 32 + lane];
        float e0 = aA + adh; e0 = (e0 >= 0.f) ? e0 : 0.2f * e0;
        float e1 = aB + adh; e1 = (e1 >= 0.f) ? e1 : 0.2f * e1;
        float w0 = __expf(e0);
        float w1 = __expf(e1);
        int j = i + 2;
        if (j + 2 <= end) {
            sA = g_es[j]; sB = g_es[j + 1];
            aA = __ldg(&g_asrc[sA * 4 + head]);
            aB = __ldg(&g_asrc[sB * 4 + head]);
        }
        wsum += w0 + w1;
        acc_edge2(w0, u0, a0, a1);
        acc_edge2(w1, u1, a0, a1);
        i = j;
    }
    if (i < end) {
        int s0 = g_es[i];
        float e0 = __ldg(&g_asrc[s0 * 4 + head]) + adh;
        e0 = (e0 >= 0.f) ? e0 : 0.2f * e0;
        float w0 = __expf(e0);
        uint4 u0 = h16[(size_t)s0 * 32 + lane];
        wsum += w0;
        acc_edge2(w0, u0, a0, a1);
    }
}

// normalize + head-mean; returns the 8 output components for lanes 0..7
__device__ __forceinline__ void agg_reduce(float4& a0, float4& a1, float wsum) {
    float nrm = 1.f / wsum;
    a0.x *= nrm; a0.y *= nrm; a0.z *= nrm; a0.w *= nrm;
    a1.x *= nrm; a1.y *= nrm; a1.z *= nrm; a1.w *= nrm;
#pragma unroll
    for (int o = 8; o <= 16; o <<= 1) {
        a0.x += __shfl_xor_sync(0xffffffffu, a0.x, o);
        a0.y += __shfl_xor_sync(0xffffffffu, a0.y, o);
        a0.z += __shfl_xor_sync(0xffffffffu, a0.z, o);
        a0.w += __shfl_xor_sync(0xffffffffu, a0.w, o);
        a1.x += __shfl_xor_sync(0xffffffffu, a1.x, o);
        a1.y += __shfl_xor_sync(0xffffffffu, a1.y, o);
        a1.z += __shfl_xor_sync(0xffffffffu, a1.z, o);
        a1.w += __shfl_xor_sync(0xffffffffu, a1.w, o);
    }
}

// ---------------- layer-1 agg: writes feat1 -------------------------------
__global__ void __launch_bounds__(256) k_agg(const float* __restrict__ bias,
                                             float* __restrict__ outf) {
    int gw = (blockIdx.x * blockDim.x + threadIdx.x) >> 5;
    int lane = threadIdx.x & 31;
    if (gw >= NN) return;
    int head = lane >> 3;

    float4 a0 = {0.f, 0.f, 0.f, 0.f}, a1 = {0.f, 0.f, 0.f, 0.f};
    float wsum = 0.f;
    agg_loop(gw, lane, head, a0, a1, wsum);
    agg_reduce(a0, a1, wsum);

    if (lane < 8) {
        float4 b0 = *(const float4*)&bias[lane * 8];
        float4 b1 = *(const float4*)&bias[lane * 8 + 4];
        float v;
        float4 o0, o1;
        v = 0.25f * a0.x + b0.x; o0.x = (v > 0.f) ? v : (__expf(v) - 1.f);
        v = 0.25f * a0.y + b0.y; o0.y = (v > 0.f) ? v : (__expf(v) - 1.f);
        v = 0.25f * a0.z + b0.z; o0.z = (v > 0.f) ? v : (__expf(v) - 1.f);
        v = 0.25f * a0.w + b0.w; o0.w = (v > 0.f) ? v : (__expf(v) - 1.f);
        v = 0.25f * a1.x + b1.x; o1.x = (v > 0.f) ? v : (__expf(v) - 1.f);
        v = 0.25f * a1.y + b1.y; o1.y = (v > 0.f) ? v : (__expf(v) - 1.f);
        v = 0.25f * a1.z + b1.z; o1.z = (v > 0.f) ? v : (__expf(v) - 1.f);
        v = 0.25f * a1.w + b1.w; o1.w = (v > 0.f) ? v : (__expf(v) - 1.f);
        float4* op = (float4*)&outf[gw * HID + lane * 8];
        op[0] = o0;
        op[1] = o1;
    }
}

// ---------------- layer-2 agg + fused scorer MLP: writes logits -----------
__global__ void __launch_bounds__(256) k_agg_sc(
    const float* __restrict__ bias, const float* __restrict__ donor,
    const float* __restrict__ Ws1,  const float* __restrict__ bs1,
    const float* __restrict__ Ws2,  const float* __restrict__ bs2,
    float* __restrict__ out) {
    __shared__ float sW1[96 * 64];   // 24 KB
    __shared__ float sW2[64];
    __shared__ float sB[64];
    __shared__ float sD[32];
    __shared__ float sFeat[8][64];   // per-warp staged features

    int t = threadIdx.x;
    for (int i = t; i < 96 * 64; i += 256) sW1[i] = Ws1[i];
    if (t < 64) { sW2[t] = Ws2[t]; sB[t] = bs1[t]; }
    if (t < 32) sD[t] = donor[t];
    __syncthreads();

    int gw = (blockIdx.x * blockDim.x + t) >> 5;
    int warp = t >> 5;
    int lane = t & 31;
    if (gw >= NN) return;
    int head = lane >> 3;

    float4 a0 = {0.f, 0.f, 0.f, 0.f}, a1 = {0.f, 0.f, 0.f, 0.f};
    float wsum = 0.f;
    agg_loop(gw, lane, head, a0, a1, wsum);
    agg_reduce(a0, a1, wsum);

    // ELU epilogue -> stage feat into smem (lanes 0..7 own 8 comps each)
    if (lane < 8) {
        float4 b0 = *(const float4*)&bias[lane * 8];
        float4 b1 = *(const float4*)&bias[lane * 8 + 4];
        float* fp = &sFeat[warp][lane * 8];
        float v;
        v = 0.25f * a0.x + b0.x; fp[0] = (v > 0.f) ? v : (__expf(v) - 1.f);
        v = 0.25f * a0.y + b0.y; fp[1] = (v > 0.f) ? v : (__expf(v) - 1.f);
        v = 0.25f * a0.z + b0.z; fp[2] = (v > 0.f) ? v : (__expf(v) - 1.f);
        v = 0.25f * a0.w + b0.w; fp[3] = (v > 0.f) ? v : (__expf(v) - 1.f);
        v = 0.25f * a1.x + b1.x; fp[4] = (v > 0.f) ? v : (__expf(v) - 1.f);
        v = 0.25f * a1.y + b1.y; fp[5] = (v > 0.f) ? v : (__expf(v) - 1.f);
        v = 0.25f * a1.z + b1.z; fp[6] = (v > 0.f) ? v : (__expf(v) - 1.f);
        v = 0.25f * a1.w + b1.w; fp[7] = (v > 0.f) ? v : (__expf(v) - 1.f);
    }
    __syncwarp();

    // scorer MLP: lane computes hidden units lane and lane+32
    float h0 = sB[lane], h1 = sB[lane + 32];
    const float* fw = sFeat[warp];
#pragma unroll 8
    for (int k = 0; k < 64; k++) {
        float xk = fw[k];
        h0 = fmaf(xk, sW1[k * 64 + lane], h0);
        h1 = fmaf(xk, sW1[k * 64 + 32 + lane], h1);
    }
#pragma unroll 8
    for (int k = 0; k < 32; k++) {
        float xk = sD[k];
        h0 = fmaf(xk, sW1[(k + 64) * 64 + lane], h0);
        h1 = fmaf(xk, sW1[(k + 64) * 64 + 32 + lane], h1);
    }
    h0 = fmaxf(h0, 0.f);
    h1 = fmaxf(h1, 0.f);
    float p = h0 * sW2[lane] + h1 * sW2[lane + 32];
#pragma unroll
    for (int o = 16; o > 0; o >>= 1) p += __shfl_xor_sync(0xffffffffu, p, o);
    if (lane == 0) out[gw] = p + bs2[0];
}

// ---------------- launch (forked-stream capture: CSR || layer-1 gemm) -----
extern "C" void kernel_launch(void* const* d_in, const int* in_sizes, int n_in,
                              void* d_out, int out_size) {
    const float* x     = (const float*)d_in[0];
    const int*   ei    = (const int*)  d_in[1];
    const float* donor = (const float*)d_in[2];
    const float* W1    = (const float*)d_in[3];
    const float* as1   = (const float*)d_in[4];
    const float* ad1   = (const float*)d_in[5];
    const float* b1    = (const float*)d_in[6];
    const float* W2    = (const float*)d_in[7];
    const float* as2   = (const float*)d_in[8];
    const float* ad2   = (const float*)d_in[9];
    const float* b2    = (const float*)d_in[10];
    const float* Ws1   = (const float*)d_in[11];
    const float* bs1   = (const float*)d_in[12];
    const float* Ws2   = (const float*)d_in[13];
    const float* bs2   = (const float*)d_in[14];
    float* out = (float*)d_out;

    float *feat1;
    cudaGetSymbolAddress((void**)&feat1, g_feat1);

    const int smem27 = 27 * FOUT * 4 + 8 * 27 * 4;
    const int smem64 = 64 * FOUT * 4 + 8 * 64 * 4;
    cudaFuncSetAttribute(k_gemm<27>, cudaFuncAttributeMaxDynamicSharedMemorySize, smem27);
    cudaFuncSetAttribute(k_gemm<64>, cudaFuncAttributeMaxDynamicSharedMemorySize, smem64);

    const int alphaGrid = (NN * 4 + 255) / 256;
    const int edgeGrid  = (ETOT + 255) / 256;
    const int aggGrid   = (NN + 7) / 8;          // warp per node, 8 warps/block

    // fork a side stream for the CSR build (independent of layer-1 GEMM)
    cudaStream_t sCSR;
    cudaEvent_t evFork, evJoin;
    cudaStreamCreateWithFlags(&sCSR, cudaStreamNonBlocking);
    cudaEventCreateWithFlags(&evFork, cudaEventDisableTiming);
    cudaEventCreateWithFlags(&evJoin, cudaEventDisableTiming);

    cudaEventRecord(evFork, 0);
    cudaStreamWaitEvent(sCSR, evFork, 0);

    // ---- CSR build on side stream ----
    k_count<<<edgeGrid, 256, 0, sCSR>>>(ei);
    k_scan1<<<NBLK, 256, 0, sCSR>>>();
    k_scan23<<<NBLK, 256, 0, sCSR>>>();
    k_scatter<<<edgeGrid, 256, 0, sCSR>>>(ei);
    cudaEventRecord(evJoin, sCSR);

    // ---- layer-1 GEMM + alpha on main stream (parallel with CSR) ----
    k_gemm<27><<<1036, 256, smem27>>>(x, W1);
    k_alpha<<<alphaGrid, 256>>>(as1, ad1);

    // join: agg needs both CSR and alpha
    cudaStreamWaitEvent(0, evJoin, 0);
    k_agg<<<aggGrid, 256>>>(b1, feat1);

    // ---- layer 2 with fused scorer ----
    k_gemm<64><<<444, 256, smem64>>>(feat1, W2);
    k_alpha<<<alphaGrid, 256>>>(as2, ad2);
    k_agg_sc<<<aggGrid, 256>>>(b2, donor, Ws1, bs1, Ws2, bs2, out);

    cudaStreamDestroy(sCSR);
    cudaEventDestroy(evFork);
    cudaEventDestroy(evJoin);
}

// round 17
// speedup vs baseline: 1.2419x; 1.1634x over previous
#include <cuda_runtime.h>
#include <cuda_fp16.h>

#define NN    50000
#define NE    800000
#define ETOT  (NE + NN)       // edges + self loops
#define FOUT  256             // HEADS * HIDDEN
#define HID   64
#define NPAD  50176           // 196 * 256
#define NBLK  196

// ---------------- scratch (device globals; no allocation allowed) ----------
__device__ __half g_hh[NN * FOUT];     // per-layer node features, fp16 [N, H*C]
__device__ float  g_asrc[NN * 4];
__device__ float  g_adst[NN * 4];
__device__ float  g_feat1[NN * HID];
__device__ float  g_weff1[27 * 8];     // W1 @ [a_src1|a_dst1]  (per head)
__device__ float  g_weff2[64 * 8];     // W2 @ [a_src2|a_dst2]

// CSR build (dst-sorted edges; built once per call, reused by both layers)
// g_cnt starts zero (static init) and is re-zeroed by k_scan23 each call.
__device__ int g_cnt[NPAD];
__device__ int g_incl[NPAD];
__device__ int g_bsum[NBLK];
__device__ int g_row[NN + 1];
__device__ int g_cur[NN];
__device__ int g_es[ETOT];             // src node ids grouped by dst

// ---------------- CSR build ------------------------------------------------
__global__ void k_count(const int* __restrict__ ei) {
    int e = blockIdx.x * blockDim.x + threadIdx.x;
    if (e >= ETOT) return;
    int dst = (e < NE) ? ei[NE + e] : (e - NE);
    atomicAdd(&g_cnt[dst], 1);
}

__global__ void k_scan1() {
    __shared__ int s[256];
    int t = threadIdx.x, i = blockIdx.x * 256 + t;
    int c = g_cnt[i];
    s[t] = c;
    __syncthreads();
#pragma unroll
    for (int off = 1; off < 256; off <<= 1) {
        int v = (t >= off) ? s[t - off] : 0;
        __syncthreads();
        s[t] += v;
        __syncthreads();
    }
    g_incl[i] = s[t];
    if (t == 255) g_bsum[blockIdx.x] = s[255];
}

__global__ void k_scan23() {
    __shared__ int s[256];
    int t = threadIdx.x;
    int b = blockIdx.x;
    s[t] = (t < b) ? g_bsum[t] : 0;
    __syncthreads();
#pragma unroll
    for (int off = 128; off > 0; off >>= 1) {
        if (t < off) s[t] += s[t + off];
        __syncthreads();
    }
    int boff = s[0];
    int i = b * 256 + t;
    int inc = g_incl[i] + boff;
    int c = g_cnt[i];
    if (i < NN) {
        g_row[i + 1] = inc;
        g_cur[i] = inc - c;
    }
    g_cnt[i] = 0;
    if (i == 0) g_row[0] = 0;
}

__global__ void k_scatter(const int* __restrict__ ei) {
    int e = blockIdx.x * blockDim.x + threadIdx.x;
    if (e >= ETOT) return;
    int src, dst;
    if (e < NE) { src = ei[e]; dst = ei[NE + e]; }
    else        { src = dst = e - NE; }
    int pos = atomicAdd(&g_cur[dst], 1);
    g_es[pos] = src;
}

// ---------------- Weff = W @ [a_src | a_dst]  (both layers, one launch) ----
// out[k][j] = sum_c W[k][(j&3)*64 + c] * a[(j&3)][c], a = a_src (j<4) / a_dst
__global__ void k_weff(const float* __restrict__ W1, const float* __restrict__ as1,
                       const float* __restrict__ ad1,
                       const float* __restrict__ W2, const float* __restrict__ as2,
                       const float* __restrict__ ad2) {
    int t = blockIdx.x * blockDim.x + threadIdx.x;
    int total = (27 + 64) * 8;
    if (t >= total) return;
    int layer2 = (t >= 27 * 8);
    int loc = layer2 ? (t - 27 * 8) : t;
    int k = loc >> 3, j = loc & 7;
    int hd = j & 3;
    const float* W = layer2 ? W2 : W1;
    const float* a = (j < 4) ? (layer2 ? as2 : as1) : (layer2 ? ad2 : ad1);
    float s = 0.f;
#pragma unroll 16
    for (int c = 0; c < 64; c++)
        s += W[k * FOUT + hd * 64 + c] * a[hd * 64 + c];
    if (layer2) g_weff2[k * 8 + j] = s;
    else        g_weff1[k * 8 + j] = s;
}

// ---------------- alphas directly from inputs: [asrc|adst] = X @ Weff ------
// warp per node; lane holds X[n][lane], X[n][lane+32]; 8 shfl-reduced dots.
template <int FIN>
__global__ void __launch_bounds__(256) k_alphax(const float* __restrict__ X,
                                                const float* __restrict__ Weff) {
    __shared__ float sW[FIN * 8];
    int t = threadIdx.x;
    for (int i = t; i < FIN * 8; i += 256) sW[i] = Weff[i];
    __syncthreads();

    int warp = t >> 5, lane = t & 31;
    int n = blockIdx.x * 8 + warp;
    if (n >= NN) return;

    float xv0 = (lane < FIN)      ? X[n * FIN + lane]      : 0.f;
    float xv1 = (lane + 32 < FIN) ? X[n * FIN + lane + 32] : 0.f;

    float r[8];
#pragma unroll
    for (int j = 0; j < 8; j++) {
        float p = 0.f;
        if (lane < FIN)      p = xv0 * sW[lane * 8 + j];
        if (lane + 32 < FIN) p += xv1 * sW[(lane + 32) * 8 + j];
#pragma unroll
        for (int o = 16; o > 0; o >>= 1)
            p += __shfl_xor_sync(0xffffffffu, p, o);
        r[j] = p;
    }
    if (lane == 0) {
        *(float4*)&g_asrc[n * 4] = make_float4(r[0], r[1], r[2], r[3]);
        *(float4*)&g_adst[n * 4] = make_float4(r[4], r[5], r[6], r[7]);
    }
}

// ---------------- feature GEMM: g_hh = fp16(X @ W)  (W: [FIN, 256]) -------
// register-prefetch double buffering (R14-validated).
template <int FIN>
__global__ void k_gemm(const float* __restrict__ X, const float* __restrict__ W) {
    extern __shared__ float sm[];
    float* Wsh = sm;                 // [FIN][256]
    float* Xs  = sm + FIN * FOUT;    // [FIN][8]
    int t = threadIdx.x;

    for (int i = t; i < FIN * (FOUT / 4); i += 256)
        ((float4*)Wsh)[i] = ((const float4*)W)[i];

    const int nTiles = (NN + 7) / 8;
    const int NLD = (8 * FIN + 255) / 256;
    float rv[2];

    int tile = blockIdx.x;
    if (tile < nTiles) {
        int n0 = tile * 8;
#pragma unroll
        for (int u = 0; u < NLD; u++) {
            int idx = t + u * 256;
            if (idx < 8 * FIN) {
                int k = idx >> 3, i = idx & 7;
                int n = n0 + i;
                rv[u] = (n < NN) ? X[n * FIN + k] : 0.f;
            }
        }
    }

    for (; tile < nTiles; tile += gridDim.x) {
        __syncthreads();
#pragma unroll
        for (int u = 0; u < NLD; u++) {
            int idx = t + u * 256;
            if (idx < 8 * FIN) Xs[idx] = rv[u];
        }
        __syncthreads();

        int nx = tile + gridDim.x;
        if (nx < nTiles) {
            int n0 = nx * 8;
#pragma unroll
            for (int u = 0; u < NLD; u++) {
                int idx = t + u * 256;
                if (idx < 8 * FIN) {
                    int k = idx >> 3, i = idx & 7;
                    int n = n0 + i;
                    rv[u] = (n < NN) ? X[n * FIN + k] : 0.f;
                }
            }
        }

        float acc[8];
#pragma unroll
        for (int i = 0; i < 8; i++) acc[i] = 0.f;
#pragma unroll
        for (int k = 0; k < FIN; k++) {
            float  w  = Wsh[k * FOUT + t];
            float4 xa = *(const float4*)&Xs[k * 8];
            float4 xb = *(const float4*)&Xs[k * 8 + 4];
            acc[0] = fmaf(xa.x, w, acc[0]);
            acc[1] = fmaf(xa.y, w, acc[1]);
            acc[2] = fmaf(xa.z, w, acc[2]);
            acc[3] = fmaf(xa.w, w, acc[3]);
            acc[4] = fmaf(xb.x, w, acc[4]);
            acc[5] = fmaf(xb.y, w, acc[5]);
            acc[6] = fmaf(xb.z, w, acc[6]);
            acc[7] = fmaf(xb.w, w, acc[7]);
        }
        int n0 = tile * 8;
#pragma unroll
        for (int i = 0; i < 8; i++) {
            int n = n0 + i;
            if (n < NN) g_hh[n * FOUT + t] = __float2half_rn(acc[i]);
        }
    }
}

// ---------------- shared edge-loop body (R12 body — frozen) ---------------
__device__ __forceinline__ void acc_edge2(float w, uint4 u,
                                          float4& a0, float4& a1) {
    float2 f;
    f = __half22float2(*(__half2*)&u.x); a0.x = fmaf(w, f.x, a0.x); a0.y = fmaf(w, f.y, a0.y);
    f = __half22float2(*(__half2*)&u.y); a0.z = fmaf(w, f.x, a0.z); a0.w = fmaf(w, f.y, a0.w);
    f = __half22float2(*(__half2*)&u.z); a1.x = fmaf(w, f.x, a1.x); a1.y = fmaf(w, f.y, a1.y);
    f = __half22float2(*(__half2*)&u.w); a1.z = fmaf(w, f.x, a1.z); a1.w = fmaf(w, f.y, a1.w);
}

__device__ __forceinline__ void agg_loop(int n, int lane, int head,
                                         float4& a0, float4& a1, float& wsum) {
    int beg = g_row[n], end = g_row[n + 1];
    float adh = __ldg(&g_adst[n * 4 + head]);
    const uint4* h16 = (const uint4*)g_hh;
    int i = beg;
    int sA = 0, sB = 0;
    float aA = 0.f, aB = 0.f;
    if (i + 2 <= end) {
        sA = g_es[i]; sB = g_es[i + 1];
        aA = __ldg(&g_asrc[sA * 4 + head]);
        aB = __ldg(&g_asrc[sB * 4 + head]);
    }
    while (i + 2 <= end) {
        uint4 u0 = h16[(size_t)sA * 32 + lane];
        uint4 u1 = h16[(size_t)sB * 32 + lane];
        float e0 = aA + adh; e0 = (e0 >= 0.f) ? e0 : 0.2f * e0;
        float e1 = aB + adh; e1 = (e1 >= 0.f) ? e1 : 0.2f * e1;
        float w0 = __expf(e0);
        float w1 = __expf(e1);
        int j = i + 2;
        if (j + 2 <= end) {
            sA = g_es[j]; sB = g_es[j + 1];
            aA = __ldg(&g_asrc[sA * 4 + head]);
            aB = __ldg(&g_asrc[sB * 4 + head]);
        }
        wsum += w0 + w1;
        acc_edge2(w0, u0, a0, a1);
        acc_edge2(w1, u1, a0, a1);
        i = j;
    }
    if (i < end) {
        int s0 = g_es[i];
        float e0 = __ldg(&g_asrc[s0 * 4 + head]) + adh;
        e0 = (e0 >= 0.f) ? e0 : 0.2f * e0;
        float w0 = __expf(e0);
        uint4 u0 = h16[(size_t)s0 * 32 + lane];
        wsum += w0;
        acc_edge2(w0, u0, a0, a1);
    }
}

__device__ __forceinline__ void agg_reduce(float4& a0, float4& a1, float wsum) {
    float nrm = 1.f / wsum;
    a0.x *= nrm; a0.y *= nrm; a0.z *= nrm; a0.w *= nrm;
    a1.x *= nrm; a1.y *= nrm; a1.z *= nrm; a1.w *= nrm;
#pragma unroll
    for (int o = 8; o <= 16; o <<= 1) {
        a0.x += __shfl_xor_sync(0xffffffffu, a0.x, o);
        a0.y += __shfl_xor_sync(0xffffffffu, a0.y, o);
        a0.z += __shfl_xor_sync(0xffffffffu, a0.z, o);
        a0.w += __shfl_xor_sync(0xffffffffu, a0.w, o);
        a1.x += __shfl_xor_sync(0xffffffffu, a1.x, o);
        a1.y += __shfl_xor_sync(0xffffffffu, a1.y, o);
        a1.z += __shfl_xor_sync(0xffffffffu, a1.z, o);
        a1.w += __shfl_xor_sync(0xffffffffu, a1.w, o);
    }
}

// ---------------- layer-1 agg: writes feat1 -------------------------------
__global__ void __launch_bounds__(256) k_agg(const float* __restrict__ bias,
                                             float* __restrict__ outf) {
    int gw = (blockIdx.x * blockDim.x + threadIdx.x) >> 5;
    int lane = threadIdx.x & 31;
    if (gw >= NN) return;
    int head = lane >> 3;

    float4 a0 = {0.f, 0.f, 0.f, 0.f}, a1 = {0.f, 0.f, 0.f, 0.f};
    float wsum = 0.f;
    agg_loop(gw, lane, head, a0, a1, wsum);
    agg_reduce(a0, a1, wsum);

    if (lane < 8) {
        float4 b0 = *(const float4*)&bias[lane * 8];
        float4 b1 = *(const float4*)&bias[lane * 8 + 4];
        float v;
        float4 o0, o1;
        v = 0.25f * a0.x + b0.x; o0.x = (v > 0.f) ? v : (__expf(v) - 1.f);
        v = 0.25f * a0.y + b0.y; o0.y = (v > 0.f) ? v : (__expf(v) - 1.f);
        v = 0.25f * a0.z + b0.z; o0.z = (v > 0.f) ? v : (__expf(v) - 1.f);
        v = 0.25f * a0.w + b0.w; o0.w = (v > 0.f) ? v : (__expf(v) - 1.f);
        v = 0.25f * a1.x + b1.x; o1.x = (v > 0.f) ? v : (__expf(v) - 1.f);
        v = 0.25f * a1.y + b1.y; o1.y = (v > 0.f) ? v : (__expf(v) - 1.f);
        v = 0.25f * a1.z + b1.z; o1.z = (v > 0.f) ? v : (__expf(v) - 1.f);
        v = 0.25f * a1.w + b1.w; o1.w = (v > 0.f) ? v : (__expf(v) - 1.f);
        float4* op = (float4*)&outf[gw * HID + lane * 8];
        op[0] = o0;
        op[1] = o1;
    }
}

// ---------------- layer-2 agg + fused scorer MLP: writes logits -----------
__global__ void __launch_bounds__(256) k_agg_sc(
    const float* __restrict__ bias, const float* __restrict__ donor,
    const float* __restrict__ Ws1,  const float* __restrict__ bs1,
    const float* __restrict__ Ws2,  const float* __restrict__ bs2,
    float* __restrict__ out) {
    __shared__ float sW1[96 * 64];   // 24 KB
    __shared__ float sW2[64];
    __shared__ float sB[64];
    __shared__ float sD[32];
    __shared__ float sFeat[8][64];

    int t = threadIdx.x;
    for (int i = t; i < 96 * 64; i += 256) sW1[i] = Ws1[i];
    if (t < 64) { sW2[t] = Ws2[t]; sB[t] = bs1[t]; }
    if (t < 32) sD[t] = donor[t];
    __syncthreads();

    int gw = (blockIdx.x * blockDim.x + t) >> 5;
    int warp = t >> 5;
    int lane = t & 31;
    if (gw >= NN) return;
    int head = lane >> 3;

    float4 a0 = {0.f, 0.f, 0.f, 0.f}, a1 = {0.f, 0.f, 0.f, 0.f};
    float wsum = 0.f;
    agg_loop(gw, lane, head, a0, a1, wsum);
    agg_reduce(a0, a1, wsum);

    if (lane < 8) {
        float4 b0 = *(const float4*)&bias[lane * 8];
        float4 b1 = *(const float4*)&bias[lane * 8 + 4];
        float* fp = &sFeat[warp][lane * 8];
        float v;
        v = 0.25f * a0.x + b0.x; fp[0] = (v > 0.f) ? v : (__expf(v) - 1.f);
        v = 0.25f * a0.y + b0.y; fp[1] = (v > 0.f) ? v : (__expf(v) - 1.f);
        v = 0.25f * a0.z + b0.z; fp[2] = (v > 0.f) ? v : (__expf(v) - 1.f);
        v = 0.25f * a0.w + b0.w; fp[3] = (v > 0.f) ? v : (__expf(v) - 1.f);
        v = 0.25f * a1.x + b1.x; fp[4] = (v > 0.f) ? v : (__expf(v) - 1.f);
        v = 0.25f * a1.y + b1.y; fp[5] = (v > 0.f) ? v : (__expf(v) - 1.f);
        v = 0.25f * a1.z + b1.z; fp[6] = (v > 0.f) ? v : (__expf(v) - 1.f);
        v = 0.25f * a1.w + b1.w; fp[7] = (v > 0.f) ? v : (__expf(v) - 1.f);
    }
    __syncwarp();

    float h0 = sB[lane], h1 = sB[lane + 32];
    const float* fw = sFeat[warp];
#pragma unroll 8
    for (int k = 0; k < 64; k++) {
        float xk = fw[k];
        h0 = fmaf(xk, sW1[k * 64 + lane], h0);
        h1 = fmaf(xk, sW1[k * 64 + 32 + lane], h1);
    }
#pragma unroll 8
    for (int k = 0; k < 32; k++) {
        float xk = sD[k];
        h0 = fmaf(xk, sW1[(k + 64) * 64 + lane], h0);
        h1 = fmaf(xk, sW1[(k + 64) * 64 + 32 + lane], h1);
    }
    h0 = fmaxf(h0, 0.f);
    h1 = fmaxf(h1, 0.f);
    float p = h0 * sW2[lane] + h1 * sW2[lane + 32];
#pragma unroll
    for (int o = 16; o > 0; o >>= 1) p += __shfl_xor_sync(0xffffffffu, p, o);
    if (lane == 0) out[gw] = p + bs2[0];
}

// ---------------- launch: 3-way fork (CSR || alphas || gemm) --------------
extern "C" void kernel_launch(void* const* d_in, const int* in_sizes, int n_in,
                              void* d_out, int out_size) {
    const float* x     = (const float*)d_in[0];
    const int*   ei    = (const int*)  d_in[1];
    const float* donor = (const float*)d_in[2];
    const float* W1    = (const float*)d_in[3];
    const float* as1   = (const float*)d_in[4];
    const float* ad1   = (const float*)d_in[5];
    const float* b1    = (const float*)d_in[6];
    const float* W2    = (const float*)d_in[7];
    const float* as2   = (const float*)d_in[8];
    const float* ad2   = (const float*)d_in[9];
    const float* b2    = (const float*)d_in[10];
    const float* Ws1   = (const float*)d_in[11];
    const float* bs1   = (const float*)d_in[12];
    const float* Ws2   = (const float*)d_in[13];
    const float* bs2   = (const float*)d_in[14];
    float* out = (float*)d_out;

    float *feat1, *weff1, *weff2;
    cudaGetSymbolAddress((void**)&feat1, g_feat1);
    cudaGetSymbolAddress((void**)&weff1, g_weff1);
    cudaGetSymbolAddress((void**)&weff2, g_weff2);

    const int smem27 = 27 * FOUT * 4 + 8 * 27 * 4;
    const int smem64 = 64 * FOUT * 4 + 8 * 64 * 4;
    cudaFuncSetAttribute(k_gemm<27>, cudaFuncAttributeMaxDynamicSharedMemorySize, smem27);
    cudaFuncSetAttribute(k_gemm<64>, cudaFuncAttributeMaxDynamicSharedMemorySize, smem64);

    const int edgeGrid  = (ETOT + 255) / 256;
    const int aggGrid   = (NN + 7) / 8;          // warp per node, 8 warps/block
    const int alxGrid   = (NN + 7) / 8;

    cudaStream_t sCSR, sAux;
    cudaEvent_t evFork, evCSR, evA1, evL2, evA2;
    cudaStreamCreateWithFlags(&sCSR, cudaStreamNonBlocking);
    cudaStreamCreateWithFlags(&sAux, cudaStreamNonBlocking);
    cudaEventCreateWithFlags(&evFork, cudaEventDisableTiming);
    cudaEventCreateWithFlags(&evCSR,  cudaEventDisableTiming);
    cudaEventCreateWithFlags(&evA1,   cudaEventDisableTiming);
    cudaEventCreateWithFlags(&evL2,   cudaEventDisableTiming);
    cudaEventCreateWithFlags(&evA2,   cudaEventDisableTiming);

    cudaEventRecord(evFork, 0);
    cudaStreamWaitEvent(sCSR, evFork, 0);
    cudaStreamWaitEvent(sAux, evFork, 0);

    // ---- CSR build on stream 1 ----
    k_count<<<edgeGrid, 256, 0, sCSR>>>(ei);
    k_scan1<<<NBLK, 256, 0, sCSR>>>();
    k_scan23<<<NBLK, 256, 0, sCSR>>>();
    k_scatter<<<edgeGrid, 256, 0, sCSR>>>(ei);
    cudaEventRecord(evCSR, sCSR);

    // ---- Weff + alpha1 on stream 2 ----
    k_weff<<<3, 256, 0, sAux>>>(W1, as1, ad1, W2, as2, ad2);
    k_alphax<27><<<alxGrid, 256, 0, sAux>>>(x, weff1);
    cudaEventRecord(evA1, sAux);

    // ---- layer-1 GEMM on main stream ----
    k_gemm<27><<<1036, 256, smem27>>>(x, W1);

    // join: agg1 needs CSR + alpha1 + g_hh(layer1)
    cudaStreamWaitEvent(0, evCSR, 0);
    cudaStreamWaitEvent(0, evA1, 0);
    k_agg<<<aggGrid, 256>>>(b1, feat1);
    cudaEventRecord(evL2, 0);

    // ---- layer 2: alpha2 (stream 2) || gemm64 (main) ----
    cudaStreamWaitEvent(sAux, evL2, 0);
    k_alphax<64><<<alxGrid, 256, 0, sAux>>>(feat1, weff2);
    cudaEventRecord(evA2, sAux);

    k_gemm<64><<<444, 256, smem64>>>(feat1, W2);

    cudaStreamWaitEvent(0, evA2, 0);
    k_agg_sc<<<aggGrid, 256>>>(b2, donor, Ws1, bs1, Ws2, bs2, out);

    cudaStreamDestroy(sCSR);
    cudaStreamDestroy(sAux);
    cudaEventDestroy(evFork);
    cudaEventDestroy(evCSR);
    cudaEventDestroy(evA1);
    cudaEventDestroy(evL2);
    cudaEventDestroy(evA2);
}